// round 7
// baseline (speedup 1.0000x reference)
#include <cuda_runtime.h>
#include <cstdint>

// ============================ problem constants ============================
constexpr int IMGC = 224;
constexpr int KTOT = IMGC * IMGC;     // 50176
constexpr int BQ   = 256;
constexpr int JN   = 25;
constexpr int TN   = 64;
constexpr int OUTN = 256;
constexpr int MIDJ = JN / 2;          // 12
constexpr int BOXC = 20;

constexpr int XG   = 56;              // x groups (grid.x)
constexpr int XPG  = 4;               // x per group: 56*4 = 224
constexpr int NCOL = 128;             // n columns per CTA (grid.y = 2 halves)
constexpr int PITCH = 225;            // 225 % 32 == 1 -> conflict-free everywhere
constexpr uint32_t SMEM_MAIN = NCOL * PITCH * 4;   // 115200 B

// ============================ scratch (device globals) =====================
__device__ __align__(256) unsigned long long g_bits[(size_t)IMGC * BQ * 4]; // 1.8MB
__device__ __align__(256) float g_part[(size_t)XG * BQ * OUTN];             // 14.7MB
__device__ int g_px[BQ * JN];
__device__ int g_ylo[BQ * JN];
__device__ int g_yhi[BQ * JN];

// ============================ kernel 1: farthest-frame box params ==========
__global__ void prep_kernel(const float* __restrict__ sk) {
    int id = blockIdx.x * blockDim.x + threadIdx.x;
    if (id >= BQ * JN) return;
    int b = id / JN, j = id % JN;
    const float* base = sk + ((size_t)b * JN + j) * TN * 3;
    const float* midb = sk + ((size_t)b * JN + MIDJ) * TN * 3;

    float best = -1.0f;
    int   tb = 0;
    for (int t = 0; t < TN; t++) {
        float dx = base[t * 3 + 0] - midb[t * 3 + 0];
        float dy = base[t * 3 + 1] - midb[t * 3 + 1];
        float dz = base[t * 3 + 2] - midb[t * 3 + 2];
        float d2 = __fadd_rn(__fadd_rn(__fmul_rn(dx, dx), __fmul_rn(dy, dy)),
                             __fmul_rn(dz, dz));
        float d = __fsqrt_rn(d2);
        if (d > best) { best = d; tb = t; }   // first-max == argmax semantics
    }
    float x = base[tb * 3 + 0];
    float y = base[tb * 3 + 1];
    int px = (int)(__fmul_rn(x, 224.0f));     // truncation == astype(int32)
    int py = (int)(__fmul_rn(y, 224.0f));
    g_px[id]  = px;
    g_ylo[id] = (py < BOXC) ? 0 : py - BOXC;
    g_yhi[id] = (py > IMGC - BOXC) ? IMGC : py + BOXC;
}

// ============================ kernel 2: per-(b,x) y-bitmask =================
__global__ void bitmask_kernel() {
    const int x = blockIdx.x;
    const int b = threadIdx.x;

    unsigned long long m[4] = {0ull, 0ull, 0ull, 0ull};
#pragma unroll
    for (int j = 0; j < JN; j++) {
        if (j == MIDJ) continue;
        int px = g_px[b * JN + j];
        if (x >= px - BOXC && x < px + BOXC) {
            int lo = g_ylo[b * JN + j];
            int hi = g_yhi[b * JN + j];
#pragma unroll
            for (int w = 0; w < 4; w++) {
                int l = lo - w * 64;  if (l < 0)  l = 0;
                int h = hi - w * 64;  if (h > 64) h = 64;
                if (l < h) {
                    unsigned long long hiM = (h == 64) ? ~0ull : ((1ull << h) - 1ull);
                    unsigned long long loM = (1ull << l) - 1ull;
                    m[w] |= hiM & ~loM;
                }
            }
        }
    }
    unsigned long long* dst = g_bits + ((size_t)x * BQ + b) * 4;
    dst[0] = m[0]; dst[1] = m[1]; dst[2] = m[2]; dst[3] = m[3];
}

// ============================ kernel 3: load / register-scan / gather =======
// grid (XG, 2); 512 threads. Per x (bulk-synchronous, 3 barriers):
//  a) load  : all warps, coalesced LDG of W columns -> S[n][y] (pitch 225)
//  b) scan  : threads 0..127, each serially prefix-sums its own column
//             (224 FADD chain in registers — no SHFL latency chain)
//  c) gather: warp w owns batches b = w+16k; uniform bit-walk of transition
//             mask D = m ^ (m>>1), alternating sign; 4 scalar LDS per event.
// Pitch 225 (== 1 mod 32) makes all three phases bank-conflict-free.
__global__ __launch_bounds__(512, 1)
void main_kernel(const float* __restrict__ W) {
    extern __shared__ float sS[];
    const int tid  = threadIdx.x;
    const int w    = tid >> 5;
    const int lane = tid & 31;
    const int xg   = blockIdx.x;
    const int n0   = blockIdx.y * NCOL;

    float4 acc[16];
#pragma unroll
    for (int k = 0; k < 16; k++) acc[k] = make_float4(0.f, 0.f, 0.f, 0.f);

    for (int i = 0; i < XPG; i++) {
        const int x = xg * XPG + i;

        // ---- (a) load: 896 warp-slots (n,s); slot = q*16 + w ----
#pragma unroll 1
        for (int q8 = 0; q8 < 7; q8++) {
            float v[8];
            int   nn[8], ss[8];
#pragma unroll
            for (int j = 0; j < 8; j++) {
                int slot = (q8 * 8 + j) * 16 + w;      // 0..895
                nn[j] = slot & 127;
                ss[j] = slot >> 7;
                v[j] = __ldg(&W[(size_t)(n0 + nn[j]) * KTOT +
                                x * IMGC + ss[j] * 32 + lane]);
            }
#pragma unroll
            for (int j = 0; j < 8; j++)
                sS[nn[j] * PITCH + ss[j] * 32 + lane] = v[j];
        }
        __syncthreads();

        // ---- (b) scan: thread t owns column n = t ----
        if (tid < NCOL) {
            float* col = sS + tid * PITCH;
            float run = 0.f;
#pragma unroll
            for (int yb = 0; yb < 14; yb++) {
                float t[16];
#pragma unroll
                for (int j = 0; j < 16; j++) t[j] = col[yb * 16 + j];
#pragma unroll
                for (int j = 0; j < 16; j++) { run += t[j]; col[yb * 16 + j] = run; }
            }
        }
        __syncthreads();

        // ---- (c) gather: warp-uniform bitmask walk ----
        {
            const float* base = sS + lane * PITCH;
#pragma unroll 1
            for (int k = 0; k < 16; k++) {
                const int b = w + 16 * k;
                const ulonglong2* mp = reinterpret_cast<const ulonglong2*>(
                    g_bits + ((size_t)x * BQ + b) * 4);
                ulonglong2 mA = __ldg(mp), mB = __ldg(mp + 1);
                unsigned long long D[4];
                D[0] = mA.x ^ ((mA.x >> 1) | (mA.y << 63));
                D[1] = mA.y ^ ((mA.y >> 1) | (mB.x << 63));
                D[2] = mB.x ^ ((mB.x >> 1) | (mB.y << 63));
                D[3] = mB.y ^ (mB.y >> 1);
                float sgn = (mA.x & 1ull) ? 1.f : -1.f;
#pragma unroll
                for (int wd = 0; wd < 4; wd++) {
                    unsigned long long d = D[wd];
                    while (d) {
                        int p = __ffsll((long long)d) - 1;
                        d &= d - 1;
                        const float* row = base + wd * 64 + p;
                        float t0 = row[0];
                        float t1 = row[32 * PITCH];
                        float t2 = row[64 * PITCH];
                        float t3 = row[96 * PITCH];
                        acc[k].x = fmaf(sgn, t0, acc[k].x);
                        acc[k].y = fmaf(sgn, t1, acc[k].y);
                        acc[k].z = fmaf(sgn, t2, acc[k].z);
                        acc[k].w = fmaf(sgn, t3, acc[k].w);
                        sgn = -sgn;
                    }
                }
            }
        }
        __syncthreads();
    }

    // ---- write partials (coalesced: 4 x 128B per warp) ----
#pragma unroll
    for (int k = 0; k < 16; k++) {
        const int b = w + 16 * k;
        float* dst = g_part + ((size_t)xg * BQ + b) * OUTN + n0 + lane;
        dst[0]  = acc[k].x;
        dst[32] = acc[k].y;
        dst[64] = acc[k].z;
        dst[96] = acc[k].w;
    }
}

// ============================ kernel 4: reduce + bias + rgb multiply ========
__global__ void final_kernel(const float* __restrict__ rgb,
                             const float* __restrict__ bias,
                             float* __restrict__ out) {
    const int b = blockIdx.x;
    const int o = threadIdx.x;
    float acc = 0.0f;
    const float* p = g_part + b * OUTN + o;
#pragma unroll
    for (int s = 0; s < XG; s++)
        acc += p[(size_t)s * (BQ * OUTN)];
    out[b * OUTN + o] = rgb[b * OUTN + o] * (acc + bias[o]);
}

// ============================ launch ========================================
extern "C" void kernel_launch(void* const* d_in, const int* in_sizes, int n_in,
                              void* d_out, int out_size) {
    const float* rgb = nullptr;
    const float* sk  = nullptr;
    const float* W   = nullptr;
    const float* bias = nullptr;
    for (int i = 0; i < n_in; i++) {
        switch (in_sizes[i]) {
            case BQ * OUTN:          rgb  = (const float*)d_in[i]; break;
            case BQ * JN * TN * 3:   sk   = (const float*)d_in[i]; break;
            case OUTN * KTOT:        W    = (const float*)d_in[i]; break;
            case OUTN:               bias = (const float*)d_in[i]; break;
            default: break;
        }
    }
    float* out = (float*)d_out;

    cudaFuncSetAttribute(main_kernel,
                         cudaFuncAttributeMaxDynamicSharedMemorySize, SMEM_MAIN);

    prep_kernel<<<(BQ * JN + 255) / 256, 256>>>(sk);
    bitmask_kernel<<<IMGC, BQ>>>();
    main_kernel<<<dim3(XG, 2), 512, SMEM_MAIN>>>(W);
    final_kernel<<<BQ, OUTN>>>(rgb, bias, out);
}